// round 5
// baseline (speedup 1.0000x reference)
#include <cuda_runtime.h>
#include <cuda_bf16.h>
#include <cstdint>
#include <math.h>

// ============================================================
// x(1024,512) f32, prototypes(100,10,512) f32, log_dist_scales(100,10,512) f32
// out(1024,100) = logsumexp_p( -( sum_d w*(x-p)^2 ) ),  w = exp(ls)
// dist[b,cp] = [x^2, x] . [w, -2wp]^T + t3[cp]
// R5: BM=128/BN=40 fused GEMM+LSE, 200 CTAs, 2 CTAs/SM (occupancy fix for
// R4's 12.5%-occ latency stall). Warp tile 16x40, acc 1x5x4.
// ============================================================

#define MB 1024
#define KD 1024

#define BM 128
#define BN 40
#define BK 64
#define NKT (KD / BK)   // 16

// ---------------- device scratch ----------------
__device__ __nv_bfloat16 g_A[MB * KD];     // [b][k]  k<512: x^2, k>=512: x
__device__ __nv_bfloat16 g_Bm[1000 * KD];  // [cp][k] k<512: w,   k>=512: -2wp
__device__ float g_t3[1000];               // sum w p^2

// ---------------- helpers ----------------
__device__ __forceinline__ uint32_t smem_u32(const void* p) {
    uint32_t a;
    asm("{ .reg .u64 t; cvta.to.shared.u64 t, %1; cvt.u32.u64 %0, t; }" : "=r"(a) : "l"(p));
    return a;
}
__device__ __forceinline__ uint32_t sw128(uint32_t off) {
    return off ^ ((off >> 3) & 0x70);
}
#define CP_ASYNC16(dst, src) \
    asm volatile("cp.async.cg.shared.global [%0], [%1], 16;" :: "r"(dst), "l"(src) : "memory")
#define CP_COMMIT() asm volatile("cp.async.commit_group;" ::: "memory")
#define CP_WAIT1()  asm volatile("cp.async.wait_group 1;" ::: "memory")
#define CP_WAIT0()  asm volatile("cp.async.wait_group 0;" ::: "memory")

#define LDMATRIX_X4(r0, r1, r2, r3, addr) \
    asm volatile("ldmatrix.sync.aligned.m8n8.x4.shared.b16 {%0,%1,%2,%3}, [%4];" \
                 : "=r"(r0), "=r"(r1), "=r"(r2), "=r"(r3) : "r"(addr))
#define LDMATRIX_X2(r0, r1, addr) \
    asm volatile("ldmatrix.sync.aligned.m8n8.x2.shared.b16 {%0,%1}, [%2];" \
                 : "=r"(r0), "=r"(r1) : "r"(addr))
#define MMA_16816(c0, c1, c2, c3, a0, a1, a2, a3, b0, b1) \
    asm volatile("mma.sync.aligned.m16n8k16.row.col.f32.bf16.bf16.f32 " \
                 "{%0,%1,%2,%3}, {%4,%5,%6,%7}, {%8,%9}, {%0,%1,%2,%3};" \
                 : "+f"(c0), "+f"(c1), "+f"(c2), "+f"(c3) \
                 : "r"(a0), "r"(a1), "r"(a2), "r"(a3), "r"(b0), "r"(b1))

// ---------------- fused prep: blocks [0,2048) do x, [2048,3048) do prototypes ----------------
__global__ void prep_kernel(const float* __restrict__ x,
                            const float* __restrict__ proto,
                            const float* __restrict__ ls) {
    if (blockIdx.x < 2048) {
        int idx = blockIdx.x * 256 + threadIdx.x;   // 0 .. 1024*512-1
        int b = idx >> 9;
        int d = idx & 511;
        float v = x[idx];
        g_A[b * KD + d]       = __float2bfloat16(v * v);
        g_A[b * KD + 512 + d] = __float2bfloat16(v);
    } else {
        int cp = blockIdx.x - 2048;   // 0..999
        int tid = threadIdx.x;        // 256
        float acc = 0.f;
        #pragma unroll
        for (int i = 0; i < 2; i++) {
            int d = tid + i * 256;
            float w = expf(ls[cp * 512 + d]);
            float p = proto[cp * 512 + d];
            g_Bm[cp * KD + d]       = __float2bfloat16(w);
            g_Bm[cp * KD + 512 + d] = __float2bfloat16(-2.0f * w * p);
            acc += w * p * p;
        }
        #pragma unroll
        for (int o = 16; o > 0; o >>= 1) acc += __shfl_xor_sync(0xffffffffu, acc, o);
        __shared__ float red[8];
        if ((tid & 31) == 0) red[tid >> 5] = acc;
        __syncthreads();
        if (tid == 0) {
            float s = 0.f;
            #pragma unroll
            for (int i = 0; i < 8; i++) s += red[i];
            g_t3[cp] = s;
        }
    }
}

// ---------------- GEMM + fused LSE ----------------
// SMEM: A[2][128][64] bf16 (SW128, 16KB each), B[2][40][64] bf16 (5KB each) = 42KB
#define SA_OFF(buf) ((buf) * 16384)
#define SB_OFF(buf) (32768 + (buf) * 5120)
#define SMEM_TOTAL  (32768 + 2 * 5120)      // 43008
#define SST_STRIDE  44                      // fp32 staging row stride (bank-dodge)
#define T3_OFF      (128 * SST_STRIDE * 4)  // 22528; t3 staging (40 floats)

__global__ __launch_bounds__(256, 2) void gemm_lse_kernel(float* __restrict__ out) {
    extern __shared__ char smem[];
    const uint32_t sbase = smem_u32(smem);
    const int tid = threadIdx.x;
    const int wid = tid >> 5;
    const int lid = tid & 31;
    const int m0 = blockIdx.y * BM;
    const int n0 = blockIdx.x * BN;

    // ---- load plan: 16B chunks. A: 128 rows x 8 = 1024 (4/thread); B: 40x8 = 320 (2/thread, guarded)
    const __nv_bfloat16* a_src[4];
    uint32_t a_dst[4];
    #pragma unroll
    for (int i = 0; i < 4; i++) {
        int q = tid + i * 256;
        int r = q >> 3, c = q & 7;
        a_src[i] = g_A + (size_t)(m0 + r) * KD + c * 8;
        a_dst[i] = sw128((uint32_t)r * 128u + (uint32_t)c * 16u);
    }
    const __nv_bfloat16* b_src[2];
    uint32_t b_dst[2];
    bool b_ok[2];
    #pragma unroll
    for (int i = 0; i < 2; i++) {
        int q = tid + i * 256;
        int r = q >> 3, c = q & 7;
        b_ok[i] = (q < 320);
        b_src[i] = g_Bm + (size_t)(n0 + (b_ok[i] ? r : 0)) * KD + c * 8;
        b_dst[i] = sw128((uint32_t)(b_ok[i] ? r : 0) * 128u + (uint32_t)c * 16u);
    }

    // warp layout: 8 warps stacked in M; warp tile 16 x 40
    const int wm = wid * 16;

    float acc[5][4];
    #pragma unroll
    for (int nf = 0; nf < 5; nf++)
        #pragma unroll
        for (int i = 0; i < 4; i++) acc[nf][i] = 0.f;

    // ldmatrix swizzled offsets
    const int l4 = lid & 15;
    uint32_t a_lm_off[4];   // [ks]
    uint32_t b_lm_off[5][4];
    #pragma unroll
    for (int ks = 0; ks < 4; ks++) {
        uint32_t r = wm + (lid & 15);
        uint32_t ch = ks * 2 + (lid >> 4);
        a_lm_off[ks] = sw128(r * 128u + ch * 16u);
    }
    #pragma unroll
    for (int nf = 0; nf < 5; nf++)
        #pragma unroll
        for (int ks = 0; ks < 4; ks++) {
            uint32_t r = nf * 8 + (l4 & 7);
            uint32_t ch = ks * 2 + (l4 >> 3);
            b_lm_off[nf][ks] = sw128(r * 128u + ch * 16u);
        }

    // ---- prologue: tile 0 ----
    {
        uint32_t sa = sbase + SA_OFF(0), sb = sbase + SB_OFF(0);
        #pragma unroll
        for (int i = 0; i < 4; i++) CP_ASYNC16(sa + a_dst[i], a_src[i]);
        #pragma unroll
        for (int i = 0; i < 2; i++) if (b_ok[i]) CP_ASYNC16(sb + b_dst[i], b_src[i]);
        CP_COMMIT();
    }

    for (int kt = 0; kt < NKT; kt++) {
        if (kt + 1 < NKT) {
            int nb = (kt + 1) & 1;
            uint32_t sa = sbase + SA_OFF(nb), sb = sbase + SB_OFF(nb);
            #pragma unroll
            for (int i = 0; i < 4; i++) CP_ASYNC16(sa + a_dst[i], a_src[i] + (kt + 1) * BK);
            #pragma unroll
            for (int i = 0; i < 2; i++) if (b_ok[i]) CP_ASYNC16(sb + b_dst[i], b_src[i] + (kt + 1) * BK);
            CP_COMMIT();
            CP_WAIT1();
        } else {
            CP_WAIT0();
        }
        __syncthreads();

        const uint32_t sa = sbase + SA_OFF(kt & 1);
        const uint32_t sb = sbase + SB_OFF(kt & 1);
        #pragma unroll
        for (int ks = 0; ks < 4; ks++) {
            uint32_t a[4], b[5][2];
            LDMATRIX_X4(a[0], a[1], a[2], a[3], sa + a_lm_off[ks]);
            #pragma unroll
            for (int nf = 0; nf < 5; nf++)
                LDMATRIX_X2(b[nf][0], b[nf][1], sb + b_lm_off[nf][ks]);
            #pragma unroll
            for (int nf = 0; nf < 5; nf++)
                MMA_16816(acc[nf][0], acc[nf][1], acc[nf][2], acc[nf][3],
                          a[0], a[1], a[2], a[3], b[nf][0], b[nf][1]);
        }
        __syncthreads();
    }

    // ---- fused epilogue: fragments -> SMEM stage -> per-(row,class) logsumexp ----
    float* sst = reinterpret_cast<float*>(smem);            // [128][44]
    float* st3 = reinterpret_cast<float*>(smem + T3_OFF);   // [40]
    if (tid < 40) st3[tid] = g_t3[n0 + tid];

    const int qr = lid >> 2;        // 0..7
    const int qc = (lid & 3) * 2;   // 0,2,4,6
    {
        int row = wm + qr;
        #pragma unroll
        for (int nf = 0; nf < 5; nf++) {
            int col = nf * 8 + qc;
            *reinterpret_cast<float2*>(&sst[row * SST_STRIDE + col]) =
                make_float2(acc[nf][0], acc[nf][1]);
            *reinterpret_cast<float2*>(&sst[(row + 8) * SST_STRIDE + col]) =
                make_float2(acc[nf][2], acc[nf][3]);
        }
    }
    __syncthreads();

    // 128 rows x 4 classes = 512 tasks, 2 per thread
    const int c0 = blockIdx.x * 4;  // first class index of this tile
    #pragma unroll
    for (int i = 0; i < 2; i++) {
        int task = tid + i * 256;
        int row = task >> 2;
        int cls = task & 3;
        const float* sp = &sst[row * SST_STRIDE + cls * 10];
        const float* tp = &st3[cls * 10];
        float v[10], mx = -3.4e38f;
        #pragma unroll
        for (int p = 0; p < 10; p++) {
            v[p] = -(sp[p] + tp[p]);
            mx = fmaxf(mx, v[p]);
        }
        float s = 0.f;
        #pragma unroll
        for (int p = 0; p < 10; p++) s += expf(v[p] - mx);
        out[(size_t)(m0 + row) * 100 + c0 + cls] = mx + logf(s);
    }
}

// ---------------- launch ----------------
extern "C" void kernel_launch(void* const* d_in, const int* in_sizes, int n_in,
                              void* d_out, int out_size) {
    const float* x     = (const float*)d_in[0];  // (1024, 512)
    const float* proto = (const float*)d_in[1];  // (100, 10, 512)
    const float* ls    = (const float*)d_in[2];  // (100, 10, 512)
    float* out = (float*)d_out;                  // (1024, 100)

    cudaFuncSetAttribute(gemm_lse_kernel, cudaFuncAttributeMaxDynamicSharedMemorySize, SMEM_TOTAL);

    prep_kernel<<<3048, 256>>>(x, proto, ls);
    gemm_lse_kernel<<<dim3(25, MB / BM), 256, SMEM_TOTAL>>>(out);
}

// round 6
// speedup vs baseline: 1.0435x; 1.0435x over previous
#include <cuda_runtime.h>
#include <cuda_bf16.h>
#include <cstdint>
#include <math.h>

// ============================================================
// x(1024,512) f32, prototypes(100,10,512) f32, log_dist_scales(100,10,512) f32
// out(1024,100) = logsumexp_p( -( sum_d w*(x-p)^2 ) ),  w = exp(ls)
// dist[b,cp] = [x^2, x] . [w, -2wp]^T + t3[cp]
// R6: 4-stage cp.async pipeline (depth-3 prefetch), 1 sync/iter, batched
// B ldmatrix (x4), vectorized prep. BM=128/BN=40, 200 CTAs, 2/SM.
// ============================================================

#define MB 1024
#define KD 1024

#define BM 128
#define BN 40
#define BK 64
#define NKT (KD / BK)   // 16

// ---------------- device scratch ----------------
__device__ __nv_bfloat16 g_A[MB * KD];     // [b][k]  k<512: x^2, k>=512: x
__device__ __nv_bfloat16 g_Bm[1000 * KD];  // [cp][k] k<512: w,   k>=512: -2wp
__device__ float g_t3[1000];               // sum w p^2

// ---------------- helpers ----------------
__device__ __forceinline__ uint32_t smem_u32(const void* p) {
    uint32_t a;
    asm("{ .reg .u64 t; cvta.to.shared.u64 t, %1; cvt.u32.u64 %0, t; }" : "=r"(a) : "l"(p));
    return a;
}
__device__ __forceinline__ uint32_t sw128(uint32_t off) {
    return off ^ ((off >> 3) & 0x70);
}
#define CP_ASYNC16(dst, src) \
    asm volatile("cp.async.cg.shared.global [%0], [%1], 16;" :: "r"(dst), "l"(src) : "memory")
#define CP_COMMIT() asm volatile("cp.async.commit_group;" ::: "memory")
#define CP_WAIT2()  asm volatile("cp.async.wait_group 2;" ::: "memory")
#define CP_WAIT1()  asm volatile("cp.async.wait_group 1;" ::: "memory")
#define CP_WAIT0()  asm volatile("cp.async.wait_group 0;" ::: "memory")

#define LDMATRIX_X4(r0, r1, r2, r3, addr) \
    asm volatile("ldmatrix.sync.aligned.m8n8.x4.shared.b16 {%0,%1,%2,%3}, [%4];" \
                 : "=r"(r0), "=r"(r1), "=r"(r2), "=r"(r3) : "r"(addr))
#define LDMATRIX_X2(r0, r1, addr) \
    asm volatile("ldmatrix.sync.aligned.m8n8.x2.shared.b16 {%0,%1}, [%2];" \
                 : "=r"(r0), "=r"(r1) : "r"(addr))
#define MMA_16816(c0, c1, c2, c3, a0, a1, a2, a3, b0, b1) \
    asm volatile("mma.sync.aligned.m16n8k16.row.col.f32.bf16.bf16.f32 " \
                 "{%0,%1,%2,%3}, {%4,%5,%6,%7}, {%8,%9}, {%0,%1,%2,%3};" \
                 : "+f"(c0), "+f"(c1), "+f"(c2), "+f"(c3) \
                 : "r"(a0), "r"(a1), "r"(a2), "r"(a3), "r"(b0), "r"(b1))

// ---------------- vectorized prep ----------------
// blocks [0,512): x -> g_A (float4 per thread)
// blocks [512,1512): prototypes -> g_Bm + t3 (float2 per thread)
__global__ void prep_kernel(const float* __restrict__ x,
                            const float* __restrict__ proto,
                            const float* __restrict__ ls) {
    if (blockIdx.x < 512) {
        int idx = blockIdx.x * 256 + threadIdx.x;   // float4 index, 0..131071
        int b  = idx >> 7;                          // 128 float4 per row
        int d0 = (idx & 127) * 4;
        float4 v = reinterpret_cast<const float4*>(x)[idx];
        __nv_bfloat162* a0 = reinterpret_cast<__nv_bfloat162*>(g_A + b * KD + d0);
        __nv_bfloat162* a1 = reinterpret_cast<__nv_bfloat162*>(g_A + b * KD + 512 + d0);
        a0[0] = __floats2bfloat162_rn(v.x * v.x, v.y * v.y);
        a0[1] = __floats2bfloat162_rn(v.z * v.z, v.w * v.w);
        a1[0] = __floats2bfloat162_rn(v.x, v.y);
        a1[1] = __floats2bfloat162_rn(v.z, v.w);
    } else {
        int cp  = blockIdx.x - 512;   // 0..999
        int tid = threadIdx.x;        // 256, each a float2 (512 d total)
        int d0  = tid * 2;
        float2 lw = *reinterpret_cast<const float2*>(ls + cp * 512 + d0);
        float2 pp = *reinterpret_cast<const float2*>(proto + cp * 512 + d0);
        float w0 = expf(lw.x), w1 = expf(lw.y);
        *reinterpret_cast<__nv_bfloat162*>(g_Bm + cp * KD + d0) =
            __floats2bfloat162_rn(w0, w1);
        *reinterpret_cast<__nv_bfloat162*>(g_Bm + cp * KD + 512 + d0) =
            __floats2bfloat162_rn(-2.0f * w0 * pp.x, -2.0f * w1 * pp.y);
        float acc = w0 * pp.x * pp.x + w1 * pp.y * pp.y;
        #pragma unroll
        for (int o = 16; o > 0; o >>= 1) acc += __shfl_xor_sync(0xffffffffu, acc, o);
        __shared__ float red[8];
        if ((tid & 31) == 0) red[tid >> 5] = acc;
        __syncthreads();
        if (tid == 0) {
            float s = 0.f;
            #pragma unroll
            for (int i = 0; i < 8; i++) s += red[i];
            g_t3[cp] = s;
        }
    }
}

// ---------------- GEMM + fused LSE ----------------
// SMEM: A[4][128][64] bf16 (SW128, 16KB each), B[4][40][64] bf16 (5KB each) = 84KB
#define SA_OFF(s) ((s) * 16384)
#define SB_OFF(s) (65536 + (s) * 5120)
#define SMEM_TOTAL  (65536 + 4 * 5120)      // 86016
#define SST_STRIDE  44                      // fp32 staging row stride
#define T3_OFF      (128 * SST_STRIDE * 4)  // 22528

__global__ __launch_bounds__(256, 2) void gemm_lse_kernel(float* __restrict__ out) {
    extern __shared__ char smem[];
    const uint32_t sbase = smem_u32(smem);
    const int tid = threadIdx.x;
    const int wid = tid >> 5;
    const int lid = tid & 31;
    const int m0 = blockIdx.y * BM;
    const int n0 = blockIdx.x * BN;

    // ---- load plan: 16B chunks. A: 1024 (4/thread); B: 320 (2/thread, guarded)
    const __nv_bfloat16* a_src[4];
    uint32_t a_dst[4];
    #pragma unroll
    for (int i = 0; i < 4; i++) {
        int q = tid + i * 256;
        int r = q >> 3, c = q & 7;
        a_src[i] = g_A + (size_t)(m0 + r) * KD + c * 8;
        a_dst[i] = sw128((uint32_t)r * 128u + (uint32_t)c * 16u);
    }
    const __nv_bfloat16* b_src[2];
    uint32_t b_dst[2];
    bool b_ok[2];
    #pragma unroll
    for (int i = 0; i < 2; i++) {
        int q = tid + i * 256;
        int r = q >> 3, c = q & 7;
        b_ok[i] = (q < 320);
        b_src[i] = g_Bm + (size_t)(n0 + (b_ok[i] ? r : 0)) * KD + c * 8;
        b_dst[i] = sw128((uint32_t)(b_ok[i] ? r : 0) * 128u + (uint32_t)c * 16u);
    }

    // warp layout: 8 warps stacked in M; warp tile 16 x 40
    const int wm = wid * 16;

    float acc[5][4];
    #pragma unroll
    for (int nf = 0; nf < 5; nf++)
        #pragma unroll
        for (int i = 0; i < 4; i++) acc[nf][i] = 0.f;

    // ldmatrix swizzled offsets
    const int l4 = lid & 15;
    uint32_t a_lm_off[4];      // A x4 per ks
    uint32_t b4_off[2][4];     // B x4 pair j covers nf=2j,2j+1
    uint32_t b2_off[4];        // B x2 covers nf=4
    #pragma unroll
    for (int ks = 0; ks < 4; ks++) {
        {
            uint32_t r = wm + (lid & 15);
            uint32_t ch = ks * 2 + (lid >> 4);
            a_lm_off[ks] = sw128(r * 128u + ch * 16u);
        }
        #pragma unroll
        for (int j = 0; j < 2; j++) {
            uint32_t r = j * 16 + (lid >> 4) * 8 + (lid & 7);
            uint32_t ch = ks * 2 + ((lid >> 3) & 1);
            b4_off[j][ks] = sw128(r * 128u + ch * 16u);
        }
        {
            uint32_t r = 32 + (l4 & 7);
            uint32_t ch = ks * 2 + (l4 >> 3);
            b2_off[ks] = sw128(r * 128u + ch * 16u);
        }
    }

    // ---- prologue: stages 0,1,2 ----
    #pragma unroll
    for (int s = 0; s < 3; s++) {
        uint32_t sa = sbase + SA_OFF(s), sb = sbase + SB_OFF(s);
        #pragma unroll
        for (int i = 0; i < 4; i++) CP_ASYNC16(sa + a_dst[i], a_src[i] + s * BK);
        #pragma unroll
        for (int i = 0; i < 2; i++) if (b_ok[i]) CP_ASYNC16(sb + b_dst[i], b_src[i] + s * BK);
        CP_COMMIT();
    }

    for (int kt = 0; kt < NKT; kt++) {
        if (kt <= NKT - 3)      CP_WAIT2();
        else if (kt == NKT - 2) CP_WAIT1();
        else                    CP_WAIT0();
        __syncthreads();

        if (kt + 3 < NKT) {
            int nb = (kt + 3) & 3;
            uint32_t sa = sbase + SA_OFF(nb), sb = sbase + SB_OFF(nb);
            #pragma unroll
            for (int i = 0; i < 4; i++) CP_ASYNC16(sa + a_dst[i], a_src[i] + (kt + 3) * BK);
            #pragma unroll
            for (int i = 0; i < 2; i++) if (b_ok[i]) CP_ASYNC16(sb + b_dst[i], b_src[i] + (kt + 3) * BK);
            CP_COMMIT();
        }

        const uint32_t sa = sbase + SA_OFF(kt & 3);
        const uint32_t sb = sbase + SB_OFF(kt & 3);
        #pragma unroll
        for (int ks = 0; ks < 4; ks++) {
            uint32_t a[4], b[5][2];
            LDMATRIX_X4(a[0], a[1], a[2], a[3], sa + a_lm_off[ks]);
            LDMATRIX_X4(b[0][0], b[0][1], b[1][0], b[1][1], sb + b4_off[0][ks]);
            LDMATRIX_X4(b[2][0], b[2][1], b[3][0], b[3][1], sb + b4_off[1][ks]);
            LDMATRIX_X2(b[4][0], b[4][1], sb + b2_off[ks]);
            #pragma unroll
            for (int nf = 0; nf < 5; nf++)
                MMA_16816(acc[nf][0], acc[nf][1], acc[nf][2], acc[nf][3],
                          a[0], a[1], a[2], a[3], b[nf][0], b[nf][1]);
        }
    }

    // ---- fused epilogue: fragments -> SMEM stage -> per-(row,class) logsumexp ----
    // sst+st3 occupy bytes [0, 22688) = stage bufs 0/1 region; safe: last reads of
    // bufs 0/1 were k-iters 12/13, sequenced behind the top-of-iter-14/15 barriers.
    float* sst = reinterpret_cast<float*>(smem);            // [128][44]
    float* st3 = reinterpret_cast<float*>(smem + T3_OFF);   // [40]
    if (tid < 40) st3[tid] = g_t3[n0 + tid];

    const int qr = lid >> 2;        // 0..7
    const int qc = (lid & 3) * 2;   // 0,2,4,6
    {
        int row = wm + qr;
        #pragma unroll
        for (int nf = 0; nf < 5; nf++) {
            int col = nf * 8 + qc;
            *reinterpret_cast<float2*>(&sst[row * SST_STRIDE + col]) =
                make_float2(acc[nf][0], acc[nf][1]);
            *reinterpret_cast<float2*>(&sst[(row + 8) * SST_STRIDE + col]) =
                make_float2(acc[nf][2], acc[nf][3]);
        }
    }
    __syncthreads();

    // 128 rows x 4 classes = 512 tasks, 2 per thread
    const int c0 = blockIdx.x * 4;
    #pragma unroll
    for (int i = 0; i < 2; i++) {
        int task = tid + i * 256;
        int row = task >> 2;
        int cls = task & 3;
        const float* sp = &sst[row * SST_STRIDE + cls * 10];
        const float* tp = &st3[cls * 10];
        float v[10], mx = -3.4e38f;
        #pragma unroll
        for (int p = 0; p < 10; p++) {
            v[p] = -(sp[p] + tp[p]);
            mx = fmaxf(mx, v[p]);
        }
        float s = 0.f;
        #pragma unroll
        for (int p = 0; p < 10; p++) s += expf(v[p] - mx);
        out[(size_t)(m0 + row) * 100 + c0 + cls] = mx + logf(s);
    }
}

// ---------------- launch ----------------
extern "C" void kernel_launch(void* const* d_in, const int* in_sizes, int n_in,
                              void* d_out, int out_size) {
    const float* x     = (const float*)d_in[0];  // (1024, 512)
    const float* proto = (const float*)d_in[1];  // (100, 10, 512)
    const float* ls    = (const float*)d_in[2];  // (100, 10, 512)
    float* out = (float*)d_out;                  // (1024, 100)

    cudaFuncSetAttribute(gemm_lse_kernel, cudaFuncAttributeMaxDynamicSharedMemorySize, SMEM_TOTAL);

    prep_kernel<<<1512, 256>>>(x, proto, ls);
    gemm_lse_kernel<<<dim3(25, MB / BM), 256, SMEM_TOTAL>>>(out);
}